// round 1
// baseline (speedup 1.0000x reference)
#include <cuda_runtime.h>
#include <cstdint>

#define NN 100000
#define NE 1600000
#define D  128

// ---- scratch (static device globals; allocation-free) ----
__device__ int   g_rowptr[NN + 1];
__device__ int   g_cursor[NN];
__device__ int   g_col[NE];
__device__ int   g_bsum[128];
__device__ float g_agg[(size_t)NN * D];
__device__ float g_h[(size_t)NN * D];

// ---------------- CSR build ----------------
__global__ void k_zero(int n) {
    int i = blockIdx.x * blockDim.x + threadIdx.x;
    if (i < n) g_cursor[i] = 0;
}

__global__ void k_hist(const int* __restrict__ dst, int e) {
    int i = blockIdx.x * blockDim.x + threadIdx.x;
    if (i < e) atomicAdd(&g_cursor[dst[i]], 1);
}

__global__ void k_scan1(int n) {
    __shared__ int sh[1024];
    int i = blockIdx.x * 1024 + threadIdx.x;
    int v = (i < n) ? g_cursor[i] : 0;
    sh[threadIdx.x] = v;
    __syncthreads();
    for (int off = 1; off < 1024; off <<= 1) {
        int t = (threadIdx.x >= (unsigned)off) ? sh[threadIdx.x - off] : 0;
        __syncthreads();
        sh[threadIdx.x] += t;
        __syncthreads();
    }
    if (i < n) g_rowptr[i] = sh[threadIdx.x] - v;   // exclusive within block
    if (threadIdx.x == 1023) g_bsum[blockIdx.x] = sh[1023];
}

__global__ void k_scan2(int nb) {
    __shared__ int sh[128];
    int v = (threadIdx.x < (unsigned)nb) ? g_bsum[threadIdx.x] : 0;
    sh[threadIdx.x] = v;
    __syncthreads();
    for (int off = 1; off < 128; off <<= 1) {
        int t = (threadIdx.x >= (unsigned)off) ? sh[threadIdx.x - off] : 0;
        __syncthreads();
        sh[threadIdx.x] += t;
        __syncthreads();
    }
    g_bsum[threadIdx.x] = sh[threadIdx.x] - v;      // exclusive block offsets
}

__global__ void k_scan3(int n, int e) {
    int i = blockIdx.x * 1024 + threadIdx.x;
    if (i < n) {
        int r = g_rowptr[i] + g_bsum[blockIdx.x];
        g_rowptr[i] = r;
        g_cursor[i] = r;
    }
    if (blockIdx.x == 0 && threadIdx.x == 0) g_rowptr[n] = e;
}

__global__ void k_scatter(const int* __restrict__ src, const int* __restrict__ dst, int e) {
    int i = blockIdx.x * blockDim.x + threadIdx.x;
    if (i < e) {
        int p = atomicAdd(&g_cursor[dst[i]], 1);
        g_col[p] = src[i];
    }
}

// ---------------- mean aggregation: one warp per node ----------------
__global__ void k_agg(const float* __restrict__ feat, float* __restrict__ out, int n) {
    int w    = (blockIdx.x * blockDim.x + threadIdx.x) >> 5;
    int lane = threadIdx.x & 31;
    if (w >= n) return;
    int beg = g_rowptr[w], end = g_rowptr[w + 1];
    float4 acc = make_float4(0.f, 0.f, 0.f, 0.f);
    int j = beg;
    for (; j + 4 <= end; j += 4) {
        int s0 = g_col[j], s1 = g_col[j + 1], s2 = g_col[j + 2], s3 = g_col[j + 3];
        float4 v0 = ((const float4*)(feat + (size_t)s0 * D))[lane];
        float4 v1 = ((const float4*)(feat + (size_t)s1 * D))[lane];
        float4 v2 = ((const float4*)(feat + (size_t)s2 * D))[lane];
        float4 v3 = ((const float4*)(feat + (size_t)s3 * D))[lane];
        acc.x += (v0.x + v1.x) + (v2.x + v3.x);
        acc.y += (v0.y + v1.y) + (v2.y + v3.y);
        acc.z += (v0.z + v1.z) + (v2.z + v3.z);
        acc.w += (v0.w + v1.w) + (v2.w + v3.w);
    }
    for (; j < end; ++j) {
        int s = g_col[j];
        float4 v = ((const float4*)(feat + (size_t)s * D))[lane];
        acc.x += v.x; acc.y += v.y; acc.z += v.z; acc.w += v.w;
    }
    int deg = end - beg;
    float inv = 1.0f / (float)(deg > 1 ? deg : 1);
    float4 o = make_float4(acc.x * inv, acc.y * inv, acc.z * inv, acc.w * inv);
    ((float4*)(out + (size_t)w * D))[lane] = o;
}

// ---------------- fused dual GEMM: out = A0@B0 + A1@B1 + bias (opt relu) ----------------
// A: [M,128] row-major, B: [128,128] row-major, out: [M,128]
__global__ __launch_bounds__(256) void k_gemm(
    const float* __restrict__ A0, const float* __restrict__ A1,
    const float* __restrict__ B0, const float* __restrict__ B1,
    const float* __restrict__ bias, float* __restrict__ out,
    int M, int doRelu)
{
    __shared__ float As[16][132];   // padded: transposed A tile [k][row]
    __shared__ float Bs[16][128];   // B tile [k][col]

    int tid = threadIdx.x;
    int tr = tid >> 4;              // 0..15 -> output rows tr*8..tr*8+7
    int tc = tid & 15;              // 0..15 -> output cols tc*8..tc*8+7
    int m0 = blockIdx.x * 128;

    float acc[8][8];
    #pragma unroll
    for (int i = 0; i < 8; ++i)
        #pragma unroll
        for (int j = 0; j < 8; ++j) acc[i][j] = 0.f;

    #pragma unroll
    for (int pair = 0; pair < 2; ++pair) {
        const float* __restrict__ A = pair ? A1 : A0;
        const float* __restrict__ B = pair ? B1 : B0;
        for (int kt = 0; kt < 8; ++kt) {
            // load A tile (128 rows x 16 k) transposed into As
            #pragma unroll
            for (int l = 0; l < 2; ++l) {
                int idx = tid + l * 256;          // 0..511 float4 slots
                int row = idx >> 2;               // 0..127
                int c4  = idx & 3;                // 0..3
                int gr  = m0 + row;
                float4 v = make_float4(0.f, 0.f, 0.f, 0.f);
                if (gr < M)
                    v = *(const float4*)(A + (size_t)gr * D + kt * 16 + c4 * 4);
                As[c4 * 4 + 0][row] = v.x;
                As[c4 * 4 + 1][row] = v.y;
                As[c4 * 4 + 2][row] = v.z;
                As[c4 * 4 + 3][row] = v.w;
            }
            // load B tile (16 k x 128 cols)
            #pragma unroll
            for (int l = 0; l < 2; ++l) {
                int idx = tid + l * 256;
                int row = idx >> 5;               // 0..15
                int c4  = idx & 31;               // 0..31
                *(float4*)&Bs[row][c4 * 4] =
                    *(const float4*)(B + (size_t)(kt * 16 + row) * D + c4 * 4);
            }
            __syncthreads();
            #pragma unroll
            for (int k = 0; k < 16; ++k) {
                float a[8], b[8];
                #pragma unroll
                for (int i = 0; i < 8; ++i) a[i] = As[k][tr * 8 + i];
                #pragma unroll
                for (int i = 0; i < 8; ++i) b[i] = Bs[k][tc * 8 + i];
                #pragma unroll
                for (int i = 0; i < 8; ++i)
                    #pragma unroll
                    for (int j = 0; j < 8; ++j)
                        acc[i][j] += a[i] * b[j];
            }
            __syncthreads();
        }
    }

    float bv[8];
    #pragma unroll
    for (int j = 0; j < 8; ++j) bv[j] = bias[tc * 8 + j];

    #pragma unroll
    for (int i = 0; i < 8; ++i) {
        int r = m0 + tr * 8 + i;
        if (r < M) {
            float o[8];
            #pragma unroll
            for (int j = 0; j < 8; ++j) {
                float v = acc[i][j] + bv[j];
                o[j] = doRelu ? (v > 0.f ? v : 0.f) : v;
            }
            float* dst = out + (size_t)r * D + tc * 8;
            *(float4*)(dst + 0) = make_float4(o[0], o[1], o[2], o[3]);
            *(float4*)(dst + 4) = make_float4(o[4], o[5], o[6], o[7]);
        }
    }
}

// ---------------- launch ----------------
extern "C" void kernel_launch(void* const* d_in, const int* in_sizes, int n_in,
                              void* d_out, int out_size)
{
    const float* x   = (const float*)d_in[0];
    const int*   ei  = (const int*)d_in[1];
    const float* W1l = (const float*)d_in[2];
    const float* b1  = (const float*)d_in[3];
    const float* W1r = (const float*)d_in[4];
    const float* W2l = (const float*)d_in[5];
    const float* b2  = (const float*)d_in[6];
    const float* W2r = (const float*)d_in[7];
    float* out = (float*)d_out;

    int N = in_sizes[0] / D;
    int E = in_sizes[1] / 2;
    const int* src = ei;
    const int* dst = ei + E;

    float *agg_ptr = nullptr, *h_ptr = nullptr;
    cudaGetSymbolAddress((void**)&agg_ptr, g_agg);
    cudaGetSymbolAddress((void**)&h_ptr, g_h);

    int nb = (N + 1023) / 1024;

    k_zero   <<<(N + 255) / 256, 256>>>(N);
    k_hist   <<<(E + 255) / 256, 256>>>(dst, E);
    k_scan1  <<<nb, 1024>>>(N);
    k_scan2  <<<1, 128>>>(nb);
    k_scan3  <<<nb, 1024>>>(N, E);
    k_scatter<<<(E + 255) / 256, 256>>>(src, dst, E);

    int aggBlocks = (N * 32 + 255) / 256;
    int gemmBlocks = (N + 127) / 128;

    // layer 1: h = relu(agg(x)@W1_l + x@W1_r + b1)
    k_agg <<<aggBlocks, 256>>>(x, agg_ptr, N);
    k_gemm<<<gemmBlocks, 256>>>(agg_ptr, x, W1l, W1r, b1, h_ptr, N, 1);

    // layer 2: out = agg(h)@W2_l + h@W2_r + b2
    k_agg <<<aggBlocks, 256>>>(h_ptr, agg_ptr, N);
    k_gemm<<<gemmBlocks, 256>>>(agg_ptr, h_ptr, W2l, W2r, b2, out, N, 0);
}

// round 3
// speedup vs baseline: 1.1263x; 1.1263x over previous
#include <cuda_runtime.h>
#include <cuda_bf16.h>
#include <cstdint>

#define NN 100000
#define NE 1600000
#define D  128

typedef unsigned int u32;

// ---- scratch (static device globals; allocation-free) ----
__device__ int   g_rowptr[NN + 1];
__device__ int   g_cursor[NN];
__device__ int   g_col[NE];
__device__ int   g_bsum[128];
__device__ float g_agg[(size_t)NN * D];
__device__ float g_h[(size_t)NN * D];
// bf16 hi/lo weight operands, k-pair packed: [4 weights][64 kp][128 n] u32
__device__ __align__(16) u32 g_Bh[4][64 * 128];
__device__ __align__(16) u32 g_Bl[4][64 * 128];

// ---------------- CSR build ----------------
__global__ void k_zero(int n) {
    int i = blockIdx.x * blockDim.x + threadIdx.x;
    if (i < n) g_cursor[i] = 0;
}
__global__ void k_hist(const int* __restrict__ dst, int e) {
    int i = blockIdx.x * blockDim.x + threadIdx.x;
    if (i < e) atomicAdd(&g_cursor[dst[i]], 1);
}
__global__ void k_scan1(int n) {
    __shared__ int sh[1024];
    int i = blockIdx.x * 1024 + threadIdx.x;
    int v = (i < n) ? g_cursor[i] : 0;
    sh[threadIdx.x] = v;
    __syncthreads();
    for (int off = 1; off < 1024; off <<= 1) {
        int t = (threadIdx.x >= (unsigned)off) ? sh[threadIdx.x - off] : 0;
        __syncthreads();
        sh[threadIdx.x] += t;
        __syncthreads();
    }
    if (i < n) g_rowptr[i] = sh[threadIdx.x] - v;
    if (threadIdx.x == 1023) g_bsum[blockIdx.x] = sh[1023];
}
__global__ void k_scan2(int nb) {
    __shared__ int sh[128];
    int v = (threadIdx.x < (unsigned)nb) ? g_bsum[threadIdx.x] : 0;
    sh[threadIdx.x] = v;
    __syncthreads();
    for (int off = 1; off < 128; off <<= 1) {
        int t = (threadIdx.x >= (unsigned)off) ? sh[threadIdx.x - off] : 0;
        __syncthreads();
        sh[threadIdx.x] += t;
        __syncthreads();
    }
    g_bsum[threadIdx.x] = sh[threadIdx.x] - v;
}
__global__ void k_scan3(int n, int e) {
    int i = blockIdx.x * 1024 + threadIdx.x;
    if (i < n) {
        int r = g_rowptr[i] + g_bsum[blockIdx.x];
        g_rowptr[i] = r;
        g_cursor[i] = r;
    }
    if (blockIdx.x == 0 && threadIdx.x == 0) g_rowptr[n] = e;
}
__global__ void k_scatter(const int* __restrict__ src, const int* __restrict__ dst, int e) {
    int i = blockIdx.x * blockDim.x + threadIdx.x;
    if (i < e) {
        int p = atomicAdd(&g_cursor[dst[i]], 1);
        g_col[p] = src[i];
    }
}

// ---------------- mean aggregation: one warp per node ----------------
__global__ void k_agg(const float* __restrict__ feat, float* __restrict__ out, int n) {
    int w    = (blockIdx.x * blockDim.x + threadIdx.x) >> 5;
    int lane = threadIdx.x & 31;
    if (w >= n) return;
    int beg = g_rowptr[w], end = g_rowptr[w + 1];
    float4 acc = make_float4(0.f, 0.f, 0.f, 0.f);
    int j = beg;
    for (; j + 4 <= end; j += 4) {
        int s0 = g_col[j], s1 = g_col[j + 1], s2 = g_col[j + 2], s3 = g_col[j + 3];
        float4 v0 = ((const float4*)(feat + (size_t)s0 * D))[lane];
        float4 v1 = ((const float4*)(feat + (size_t)s1 * D))[lane];
        float4 v2 = ((const float4*)(feat + (size_t)s2 * D))[lane];
        float4 v3 = ((const float4*)(feat + (size_t)s3 * D))[lane];
        acc.x += (v0.x + v1.x) + (v2.x + v3.x);
        acc.y += (v0.y + v1.y) + (v2.y + v3.y);
        acc.z += (v0.z + v1.z) + (v2.z + v3.z);
        acc.w += (v0.w + v1.w) + (v2.w + v3.w);
    }
    for (; j < end; ++j) {
        int s = g_col[j];
        float4 v = ((const float4*)(feat + (size_t)s * D))[lane];
        acc.x += v.x; acc.y += v.y; acc.z += v.z; acc.w += v.w;
    }
    int deg = end - beg;
    float inv = 1.0f / (float)(deg > 1 ? deg : 1);
    ((float4*)(out + (size_t)w * D))[lane] =
        make_float4(acc.x * inv, acc.y * inv, acc.z * inv, acc.w * inv);
}

// ---------------- helpers ----------------
__device__ __forceinline__ u32 pack_bf16(__nv_bfloat16 lo, __nv_bfloat16 hi) {
    return (u32)__bfloat16_as_ushort(lo) | ((u32)__bfloat16_as_ushort(hi) << 16);
}
__device__ __forceinline__ void split2(float f0, float f1, u32& hpack, u32& lpack) {
    __nv_bfloat16 h0 = __float2bfloat16(f0);
    __nv_bfloat16 h1 = __float2bfloat16(f1);
    __nv_bfloat16 l0 = __float2bfloat16(f0 - __bfloat162float(h0));
    __nv_bfloat16 l1 = __float2bfloat16(f1 - __bfloat162float(h1));
    hpack = pack_bf16(h0, h1);
    lpack = pack_bf16(l0, l1);
}
__device__ __forceinline__ void mma16816(float* c, const u32* a, const u32* b) {
    asm volatile(
        "mma.sync.aligned.m16n8k16.row.col.f32.bf16.bf16.f32 "
        "{%0,%1,%2,%3}, {%4,%5,%6,%7}, {%8,%9}, {%0,%1,%2,%3};"
        : "+f"(c[0]), "+f"(c[1]), "+f"(c[2]), "+f"(c[3])
        : "r"(a[0]), "r"(a[1]), "r"(a[2]), "r"(a[3]), "r"(b[0]), "r"(b[1]));
}

// ---------------- weight prep: fp32 W[k][n] -> k-pair-packed bf16 hi/lo [kp][n] ----------------
__global__ void k_prepB(const float* __restrict__ W0, const float* __restrict__ W1,
                        const float* __restrict__ W2, const float* __restrict__ W3) {
    const float* Ws[4] = {W0, W1, W2, W3};
    const float* W = Ws[blockIdx.x];
    u32* bh = g_Bh[blockIdx.x];
    u32* bl = g_Bl[blockIdx.x];
    for (int u = threadIdx.x; u < 64 * 128; u += blockDim.x) {
        int kp = u >> 7, n = u & 127;
        float f0 = W[(2 * kp) * D + n];
        float f1 = W[(2 * kp + 1) * D + n];
        u32 hp, lp;
        split2(f0, f1, hp, lp);
        bh[u] = hp;
        bl[u] = lp;
    }
}

// ---------------- HMMA fused dual-GEMM: out = A0@W[b0] + A1@W[b1] + bias (opt relu) ----------------
// SMEM (u32 units):  Ah[128][68], Al[128][68], Bh[64][136], Bl[64][136]
#define AS 68
#define BS 136
#define SM_AH 0
#define SM_AL (SM_AH + 128 * AS)
#define SM_BH (SM_AL + 128 * AS)
#define SM_BL (SM_BH + 64 * BS)
#define SM_U32_TOTAL (SM_BL + 64 * BS)          // 34816 u32 = 139264 B

__global__ __launch_bounds__(256, 1) void k_gemm_mma(
    const float* __restrict__ A0, const float* __restrict__ A1,
    int b0, int b1,
    const float* __restrict__ bias, float* __restrict__ out,
    int M, int doRelu)
{
    extern __shared__ __align__(16) u32 sm[];
    u32* Ah = sm + SM_AH;
    u32* Al = sm + SM_AL;
    u32* Bh = sm + SM_BH;
    u32* Bl = sm + SM_BL;

    int tid = threadIdx.x, wid = tid >> 5, lane = tid & 31;
    int g = lane >> 2, tg = lane & 3;
    int wm = (wid & 1) * 64, wn = (wid >> 1) * 32;
    int m0 = blockIdx.x * 128;

    float acc[4][4][4];
    #pragma unroll
    for (int mt = 0; mt < 4; ++mt)
        #pragma unroll
        for (int nt = 0; nt < 4; ++nt)
            #pragma unroll
            for (int c = 0; c < 4; ++c) acc[mt][nt][c] = 0.f;

    #pragma unroll
    for (int pair = 0; pair < 2; ++pair) {
        const float* __restrict__ A = pair ? A1 : A0;
        const u32* __restrict__ BHg = g_Bh[pair ? b1 : b0];
        const u32* __restrict__ BLg = g_Bl[pair ? b1 : b0];

        if (pair) __syncthreads();   // protect previous-iteration reads

        // convert A tile: 128 rows x 64 kpairs
        for (int u = tid; u < 8192; u += 256) {
            int row = u >> 6, kp = u & 63;
            int gr = m0 + row;
            float2 f = make_float2(0.f, 0.f);
            if (gr < M) f = ((const float2*)(A + (size_t)gr * D))[kp];
            u32 hp, lp;
            split2(f.x, f.y, hp, lp);
            Ah[row * AS + kp] = hp;
            Al[row * AS + kp] = lp;
        }
        // copy packed B: 64 rows x 128 u32 (32 uint4 per row)
        for (int u = tid; u < 2048; u += 256) {
            int row = u >> 5, c4 = u & 31;
            *(uint4*)&Bh[row * BS + c4 * 4] = ((const uint4*)BHg)[u];
            *(uint4*)&Bl[row * BS + c4 * 4] = ((const uint4*)BLg)[u];
        }
        __syncthreads();

        #pragma unroll
        for (int term = 0; term < 3; ++term) {
            const u32* pA = (term == 1) ? Al : Ah;
            const u32* pB = (term == 2) ? Bl : Bh;
            #pragma unroll
            for (int ks = 0; ks < 8; ++ks) {
                u32 afr[4][4];
                #pragma unroll
                for (int mt = 0; mt < 4; ++mt) {
                    int r = wm + mt * 16 + g;
                    afr[mt][0] = pA[r * AS + ks * 8 + tg];
                    afr[mt][1] = pA[(r + 8) * AS + ks * 8 + tg];
                    afr[mt][2] = pA[r * AS + ks * 8 + tg + 4];
                    afr[mt][3] = pA[(r + 8) * AS + ks * 8 + tg + 4];
                }
                u32 bfr[4][2];
                #pragma unroll
                for (int nt = 0; nt < 4; ++nt) {
                    int n = wn + nt * 8 + g;
                    bfr[nt][0] = pB[(ks * 8 + tg) * BS + n];
                    bfr[nt][1] = pB[(ks * 8 + tg + 4) * BS + n];
                }
                #pragma unroll
                for (int mt = 0; mt < 4; ++mt)
                    #pragma unroll
                    for (int nt = 0; nt < 4; ++nt)
                        mma16816(acc[mt][nt], afr[mt], bfr[nt]);
            }
        }
    }

    // epilogue: C[row][col]: c0,c1 -> row base+g cols 2tg,2tg+1 ; c2,c3 -> row base+g+8
    #pragma unroll
    for (int nt = 0; nt < 4; ++nt) {
        int ccol = wn + nt * 8 + tg * 2;
        float bv0 = __ldg(bias + ccol), bv1 = __ldg(bias + ccol + 1);
        #pragma unroll
        for (int mt = 0; mt < 4; ++mt) {
            int r0 = m0 + wm + mt * 16 + g;
            float v0 = acc[mt][nt][0] + bv0, v1 = acc[mt][nt][1] + bv1;
            float v2 = acc[mt][nt][2] + bv0, v3 = acc[mt][nt][3] + bv1;
            if (doRelu) {
                v0 = v0 > 0.f ? v0 : 0.f; v1 = v1 > 0.f ? v1 : 0.f;
                v2 = v2 > 0.f ? v2 : 0.f; v3 = v3 > 0.f ? v3 : 0.f;
            }
            if (r0 < M)     *(float2*)(out + (size_t)r0 * D + ccol)       = make_float2(v0, v1);
            if (r0 + 8 < M) *(float2*)(out + (size_t)(r0 + 8) * D + ccol) = make_float2(v2, v3);
        }
    }
}

// ---------------- launch ----------------
extern "C" void kernel_launch(void* const* d_in, const int* in_sizes, int n_in,
                              void* d_out, int out_size)
{
    const float* x   = (const float*)d_in[0];
    const int*   ei  = (const int*)d_in[1];
    const float* W1l = (const float*)d_in[2];
    const float* b1  = (const float*)d_in[3];
    const float* W1r = (const float*)d_in[4];
    const float* W2l = (const float*)d_in[5];
    const float* b2  = (const float*)d_in[6];
    const float* W2r = (const float*)d_in[7];
    float* out = (float*)d_out;

    int N = in_sizes[0] / D;
    int E = in_sizes[1] / 2;
    const int* src = ei;
    const int* dst = ei + E;

    float *agg_ptr = nullptr, *h_ptr = nullptr;
    cudaGetSymbolAddress((void**)&agg_ptr, g_agg);
    cudaGetSymbolAddress((void**)&h_ptr, g_h);

    cudaFuncSetAttribute(k_gemm_mma, cudaFuncAttributeMaxDynamicSharedMemorySize,
                         SM_U32_TOTAL * 4);

    int nb = (N + 1023) / 1024;

    k_zero   <<<(N + 255) / 256, 256>>>(N);
    k_hist   <<<(E + 255) / 256, 256>>>(dst, E);
    k_scan1  <<<nb, 1024>>>(N);
    k_scan2  <<<1, 128>>>(nb);
    k_scan3  <<<nb, 1024>>>(N, E);
    k_scatter<<<(E + 255) / 256, 256>>>(src, dst, E);
    k_prepB  <<<4, 256>>>(W1l, W1r, W2l, W2r);

    int aggBlocks  = (N * 32 + 255) / 256;
    int gemmBlocks = (N + 127) / 128;

    // layer 1: h = relu(agg(x)@W1_l + x@W1_r + b1)
    k_agg     <<<aggBlocks, 256>>>(x, agg_ptr, N);
    k_gemm_mma<<<gemmBlocks, 256, SM_U32_TOTAL * 4>>>(agg_ptr, x, 0, 1, b1, h_ptr, N, 1);

    // layer 2: out = agg(h)@W2_l + h@W2_r + b2
    k_agg     <<<aggBlocks, 256>>>(h_ptr, agg_ptr, N);
    k_gemm_mma<<<gemmBlocks, 256, SM_U32_TOTAL * 4>>>(agg_ptr, h_ptr, 2, 3, b2, out, N, 0);
}